// round 11
// baseline (speedup 1.0000x reference)
#include <cuda_runtime.h>
#include <cuda_fp16.h>
#include <math.h>

#define N_IMG 2
#define CCH   256
#define HH    256
#define WW    256
#define PHB   7
#define PWB   7
#define NBINS (PHB * PWB)
#define NPHASE (NBINS * 2)
#define NROIS 1024
#define SCALE 0.25f
#define CBLK  128                 // channels per gather work item
#define NITEMS (NROIS * 2)        // (roi, channel-half) work items
#define GBLOCKS (148 * 6)         // persistent grid

// 64 MB static scratch: NHWC features in fp16 (fully L2-resident).
__device__ uint4 g_nhwc_h[(size_t)N_IMG * HH * WW * CCH / 8];

// ---------------------------------------------------------------------------
// Kernel 1: NCHW fp32 -> NHWC fp16 transpose. __ldcs input reads keep the
// streaming read from evicting the freshly written 64 MB NHWC cache.
// ---------------------------------------------------------------------------
__global__ void __launch_bounds__(256) nchw_to_nhwc_h_kernel(const float* __restrict__ in)
{
    __shared__ float4 tile[128 * 8];
    const int n   = blockIdx.z;
    const int hw0 = blockIdx.x * 128;
    const int c0  = blockIdx.y * 32;
    const int t   = threadIdx.x;

    const float* src = in + (size_t)n * CCH * HH * WW;
    __half*      dst = (__half*)g_nhwc_h + (size_t)n * HH * WW * CCH;

    const int hw4 = t & 31;
    const int c4w = t >> 5;

    float vv[4][4];
#pragma unroll
    for (int j = 0; j < 4; ++j) {
        float4 ld = __ldcs((const float4*)(src + (size_t)(c0 + c4w * 4 + j) * (HH * WW)
                                               + hw0 + hw4 * 4));
        vv[j][0] = ld.x; vv[j][1] = ld.y; vv[j][2] = ld.z; vv[j][3] = ld.w;
    }
#pragma unroll
    for (int r = 0; r < 4; ++r) {
        float4 o = make_float4(vv[0][r], vv[1][r], vv[2][r], vv[3][r]);
        const int hw = hw4 * 4 + r;
        tile[hw * 8 + (c4w ^ ((hw >> 2) & 7))] = o;
    }
    __syncthreads();

#pragma unroll
    for (int k = 0; k < 2; ++k) {
        const int idx = t + k * 256;       // 0..511
        const int cq  = idx & 3;           // 8-channel group
        const int hw  = idx >> 2;
        const int sw  = (hw >> 2) & 7;
        float4 f0 = tile[hw * 8 + ((2 * cq)     ^ sw)];
        float4 f1 = tile[hw * 8 + ((2 * cq + 1) ^ sw)];
        __half2 h[4];
        h[0] = __floats2half2_rn(f0.x, f0.y);
        h[1] = __floats2half2_rn(f0.z, f0.w);
        h[2] = __floats2half2_rn(f1.x, f1.y);
        h[3] = __floats2half2_rn(f1.z, f1.w);
        *(uint4*)(dst + (size_t)(hw0 + hw) * CCH + c0 + cq * 8) = *(uint4*)h;
    }
}

// ---------------------------------------------------------------------------
// Kernel 2: PERSISTENT rotated RoIAlign gather on fp16 NHWC (L2-resident).
// Grid = 888 blocks looping over 2048 (roi, channel-half) items (no wave
// tail). Block = 224 threads = 32 uint2-lanes x 7 bin-slices (49/7 = 7 bins
// per warp: perfect balance). Stage A hoists per-(bin,phase) indices +
// weights. Stage B: per-phase 8-deep 8B load batches + scalar fmaf (best
// measured config). fp16 smem staging (12.5 KB) -> bigger L1 carveout for
// gather reuse; conflict-free STS; coalesced streaming flush.
// ---------------------------------------------------------------------------
__global__ void __launch_bounds__(224, 6) roialign_rot_kernel(
    const float* __restrict__ rois, float* __restrict__ out)
{
    __shared__ __half s_outh[CBLK * NBINS];        // 12544 B
    __shared__ int    s_idx[NPHASE * 8];           // 3136 B
    __shared__ float  s_w  [NPHASE * 8];           // 3136 B

    const int tid    = threadIdx.x;
    const int cgrp   = tid & 31;               // uint2 channel group (4 halves)
    const int bslice = tid >> 5;               // 0..6

    for (int item = blockIdx.x; item < NITEMS; item += GBLOCKS) {
        const int roi = item >> 1;
        const int c0  = (item & 1) * CBLK;

        const float* r = rois + roi * 6;
        const int b = (int)r[0];

        // ---- Stage A: per-(bin,phase) precompute by 98 threads ----
        if (tid < NPHASE) {
            const int bin = tid >> 1;
            const int sp  = tid & 1;
            const int ph  = bin / PWB;
            const int pw  = bin - ph * PWB;

            const float cx = fmaf(r[1], SCALE, -0.5f);
            const float cy = fmaf(r[2], SCALE, -0.5f);
            const float rw = r[3] * SCALE;
            const float rh = r[4] * SCALE;
            float sn, cs;
            sincosf(r[5], &sn, &cs);

            const float bin_h = rh * (1.0f / PHB);
            const float bin_w = rw * (1.0f / PWB);
            const float yy = -0.5f * rh + ((float)ph + ((float)sp + 0.5f) * 0.5f) * bin_h;

#pragma unroll
            for (int ix = 0; ix < 2; ++ix) {
                const float xx = -0.5f * rw + ((float)pw + ((float)ix + 0.5f) * 0.5f) * bin_w;
                float y = yy * cs - xx * sn + cy;
                float x = yy * sn + xx * cs + cx;

                const bool valid = (y > -1.0f) & (y < (float)HH) &
                                   (x > -1.0f) & (x < (float)WW);
                y = fmaxf(y, 0.0f);
                x = fmaxf(x, 0.0f);

                int yl = (int)y;
                int xl = (int)x;
                int yh, xh; float ly, lx;
                if (yl >= HH - 1) { yl = HH - 1; yh = HH - 1; ly = 0.f; }
                else              { yh = yl + 1; ly = y - (float)yl; }
                if (xl >= WW - 1) { xl = WW - 1; xh = WW - 1; lx = 0.f; }
                else              { xh = xl + 1; lx = x - (float)xl; }

                const float vsc = valid ? 0.25f : 0.0f;   // folds the /4 mean
                const float hy = 1.f - ly, hx = 1.f - lx;
                const int base = tid * 8 + ix * 4;
                s_w[base + 0] = hy * hx * vsc;
                s_w[base + 1] = hy * lx * vsc;
                s_w[base + 2] = ly * hx * vsc;
                s_w[base + 3] = ly * lx * vsc;

                const int rl = yl * WW, rh2 = yh * WW;
                s_idx[base + 0] = (rl  + xl) << 6;   // * (CCH/4) uint2 units
                s_idx[base + 1] = (rl  + xh) << 6;
                s_idx[base + 2] = (rh2 + xl) << 6;
                s_idx[base + 3] = (rh2 + xh) << 6;
            }
        }
        __syncthreads();

        const uint2* __restrict__ feat =
            (const uint2*)g_nhwc_h + (size_t)b * (HH * WW * (CCH / 4))
            + (c0 / 4) + cgrp;

        // ---- Stage B: 7 bins per warp, 8-deep load batches per phase ----
        for (int bin = bslice; bin < NBINS; bin += 7) {
            float a0 = 0.f, a1 = 0.f, a2 = 0.f, a3 = 0.f;

#pragma unroll
            for (int sp = 0; sp < 2; ++sp) {
                const int base = (bin * 2 + sp) * 8;
                const int4   i01 = *(const int4*)&s_idx[base];
                const int4   i23 = *(const int4*)&s_idx[base + 4];
                const float4 w01 = *(const float4*)&s_w[base];
                const float4 w23 = *(const float4*)&s_w[base + 4];

                uint2 v[8];
                v[0] = __ldg(feat + i01.x);
                v[1] = __ldg(feat + i01.y);
                v[2] = __ldg(feat + i01.z);
                v[3] = __ldg(feat + i01.w);
                v[4] = __ldg(feat + i23.x);
                v[5] = __ldg(feat + i23.y);
                v[6] = __ldg(feat + i23.z);
                v[7] = __ldg(feat + i23.w);

                const float wf[8] = {w01.x, w01.y, w01.z, w01.w,
                                     w23.x, w23.y, w23.z, w23.w};
#pragma unroll
                for (int i = 0; i < 8; ++i) {
                    const __half2* hp = (const __half2*)&v[i];
                    float2 f0 = __half22float2(hp[0]);
                    float2 f1 = __half22float2(hp[1]);
                    a0 = fmaf(wf[i], f0.x, a0);
                    a1 = fmaf(wf[i], f0.y, a1);
                    a2 = fmaf(wf[i], f1.x, a2);
                    a3 = fmaf(wf[i], f1.y, a3);
                }
            }

            // fp16 staging: one 8B STS per bin, conflict-free.
            __half2 h2[2];
            h2[0] = __floats2half2_rn(a0, a1);
            h2[1] = __floats2half2_rn(a2, a3);
            *(uint2*)&s_outh[(cgrp * NBINS + bin) * 4] = *(uint2*)h2;
        }

        __syncthreads();
        // Flush: each thread reads one 8B LDS (4 channels of one bin),
        // converts to fp32, writes 4 coalesced scalar streaming stores.
        float* o = out + (size_t)roi * (CCH * NBINS) + (size_t)c0 * NBINS;
        for (int i = tid; i < (CBLK / 4) * NBINS; i += 224) {
            const int g  = i / NBINS;       // channel quad
            const int bb = i - g * NBINS;   // bin
            uint2 raw = *(const uint2*)&s_outh[i * 4];
            const __half2* hp = (const __half2*)&raw;
            float2 f0 = __half22float2(hp[0]);
            float2 f1 = __half22float2(hp[1]);
            float* og = o + (4 * g) * NBINS + bb;
            __stcs(og + 0 * NBINS, f0.x);
            __stcs(og + 1 * NBINS, f0.y);
            __stcs(og + 2 * NBINS, f1.x);
            __stcs(og + 3 * NBINS, f1.y);
        }
        __syncthreads();   // protect s_idx/s_w/s_outh before next item
    }
}

extern "C" void kernel_launch(void* const* d_in, const int* in_sizes, int n_in,
                              void* d_out, int out_size)
{
    const float* feat = (const float*)d_in[0];
    const float* rois = (const float*)d_in[1];
    if (in_sizes[0] == NROIS * 6) {
        rois = (const float*)d_in[0];
        feat = (const float*)d_in[1];
    }
    float* out = (float*)d_out;

    dim3 tg((HH * WW) / 128, CCH / 32, N_IMG);
    nchw_to_nhwc_h_kernel<<<tg, 256>>>(feat);

    roialign_rot_kernel<<<GBLOCKS, 224>>>(rois, out);
}

// round 13
// speedup vs baseline: 1.1570x; 1.1570x over previous
#include <cuda_runtime.h>
#include <cuda_fp16.h>
#include <math.h>

#define N_IMG 2
#define CCH   256
#define HH    256
#define WW    256
#define PHB   7
#define PWB   7
#define NBINS (PHB * PWB)
#define NPHASE (NBINS * 2)
#define NROIS 1024
#define SCALE 0.25f
#define CBLK  128                 // channels per gather block

// 64 MB static scratch: NHWC features in fp16 (L2-resident working set).
__device__ uint4 g_nhwc_h[(size_t)N_IMG * HH * WW * CCH / 8];

// 8B load with L2 evict_last policy (cache_hint form — the inline
// .L2::evict_last qualifier is width-restricted on sm_103a ptxas).
__device__ __forceinline__ uint2 ldg_el(const uint2* p, unsigned long long pol)
{
    uint2 v;
    asm("ld.global.nc.L2::cache_hint.v2.u32 {%0,%1}, [%2], %3;"
        : "=r"(v.x), "=r"(v.y) : "l"(p), "l"(pol));
    return v;
}
__device__ __forceinline__ unsigned long long mk_evict_last_policy()
{
    unsigned long long pol;
    asm("createpolicy.fractional.L2::evict_last.b64 %0, 1.0;" : "=l"(pol));
    return pol;
}

// ---------------------------------------------------------------------------
// Kernel 1: NCHW fp32 -> NHWC fp16 transpose. __ldcs input reads keep the
// streaming read from evicting the freshly written NHWC cache from L2.
// ---------------------------------------------------------------------------
__global__ void __launch_bounds__(256) nchw_to_nhwc_h_kernel(const float* __restrict__ in)
{
    __shared__ float4 tile[128 * 8];
    const int n   = blockIdx.z;
    const int hw0 = blockIdx.x * 128;
    const int c0  = blockIdx.y * 32;
    const int t   = threadIdx.x;

    const float* src = in + (size_t)n * CCH * HH * WW;
    __half*      dst = (__half*)g_nhwc_h + (size_t)n * HH * WW * CCH;

    const int hw4 = t & 31;
    const int c4w = t >> 5;

    float vv[4][4];
#pragma unroll
    for (int j = 0; j < 4; ++j) {
        float4 ld = __ldcs((const float4*)(src + (size_t)(c0 + c4w * 4 + j) * (HH * WW)
                                               + hw0 + hw4 * 4));
        vv[j][0] = ld.x; vv[j][1] = ld.y; vv[j][2] = ld.z; vv[j][3] = ld.w;
    }
#pragma unroll
    for (int r = 0; r < 4; ++r) {
        float4 o = make_float4(vv[0][r], vv[1][r], vv[2][r], vv[3][r]);
        const int hw = hw4 * 4 + r;
        tile[hw * 8 + (c4w ^ ((hw >> 2) & 7))] = o;
    }
    __syncthreads();

#pragma unroll
    for (int k = 0; k < 2; ++k) {
        const int idx = t + k * 256;       // 0..511
        const int cq  = idx & 3;           // 8-channel group
        const int hw  = idx >> 2;
        const int sw  = (hw >> 2) & 7;
        float4 f0 = tile[hw * 8 + ((2 * cq)     ^ sw)];
        float4 f1 = tile[hw * 8 + ((2 * cq + 1) ^ sw)];
        __half2 h[4];
        h[0] = __floats2half2_rn(f0.x, f0.y);
        h[1] = __floats2half2_rn(f0.z, f0.w);
        h[2] = __floats2half2_rn(f1.x, f1.y);
        h[3] = __floats2half2_rn(f1.z, f1.w);
        *(uint4*)(dst + (size_t)(hw0 + hw) * CCH + c0 + cq * 8) = *(uint4*)h;
    }
}

// ---------------------------------------------------------------------------
// Kernel 2: rotated RoIAlign gather on fp16 NHWC features. Block =
// (roi, channel-half): 128 channels, 256 threads = 32 uint2-groups x 8
// bin-slices. Stage A hoists per-(bin,phase) indices + weights. Stage B:
// per-phase 8-deep evict_last load batches + scalar fmaf. Conflict-free
// STS.128 staging; coalesced streaming flush.
// ---------------------------------------------------------------------------
__global__ void __launch_bounds__(256, 5) roialign_rot_kernel(
    const float* __restrict__ rois, float* __restrict__ out)
{
    __shared__ float4 s_out4[(CBLK / 4) * NBINS];  // 25088 B
    __shared__ int    s_idx[NPHASE * 8];           // 3136 B
    __shared__ float  s_w  [NPHASE * 8];           // 3136 B

    const int roi    = blockIdx.x;
    const int c0     = blockIdx.y * CBLK;      // 0 or 128
    const int tid    = threadIdx.x;
    const int cgrp   = tid & 31;               // uint2 channel group (4 halves)
    const int bslice = tid >> 5;               // 0..7

    const float* r = rois + roi * 6;
    const int b = (int)r[0];

    // ---- Stage A: per-(bin,phase) precompute by 98 threads ----
    if (tid < NPHASE) {
        const int bin = tid >> 1;
        const int sp  = tid & 1;
        const int ph  = bin / PWB;
        const int pw  = bin - ph * PWB;

        const float cx = fmaf(r[1], SCALE, -0.5f);
        const float cy = fmaf(r[2], SCALE, -0.5f);
        const float rw = r[3] * SCALE;
        const float rh = r[4] * SCALE;
        float sn, cs;
        sincosf(r[5], &sn, &cs);

        const float bin_h = rh * (1.0f / PHB);
        const float bin_w = rw * (1.0f / PWB);
        const float yy = -0.5f * rh + ((float)ph + ((float)sp + 0.5f) * 0.5f) * bin_h;

#pragma unroll
        for (int ix = 0; ix < 2; ++ix) {
            const float xx = -0.5f * rw + ((float)pw + ((float)ix + 0.5f) * 0.5f) * bin_w;
            float y = yy * cs - xx * sn + cy;
            float x = yy * sn + xx * cs + cx;

            const bool valid = (y > -1.0f) & (y < (float)HH) &
                               (x > -1.0f) & (x < (float)WW);
            y = fmaxf(y, 0.0f);
            x = fmaxf(x, 0.0f);

            int yl = (int)y;
            int xl = (int)x;
            int yh, xh; float ly, lx;
            if (yl >= HH - 1) { yl = HH - 1; yh = HH - 1; ly = 0.f; }
            else              { yh = yl + 1; ly = y - (float)yl; }
            if (xl >= WW - 1) { xl = WW - 1; xh = WW - 1; lx = 0.f; }
            else              { xh = xl + 1; lx = x - (float)xl; }

            const float vsc = valid ? 0.25f : 0.0f;   // folds the /4 mean
            const float hy = 1.f - ly, hx = 1.f - lx;
            const int base = tid * 8 + ix * 4;
            s_w[base + 0] = hy * hx * vsc;
            s_w[base + 1] = hy * lx * vsc;
            s_w[base + 2] = ly * hx * vsc;
            s_w[base + 3] = ly * lx * vsc;

            const int rl = yl * WW, rh2 = yh * WW;
            s_idx[base + 0] = (rl  + xl) << 6;   // * (CCH/4) uint2 units
            s_idx[base + 1] = (rl  + xh) << 6;
            s_idx[base + 2] = (rh2 + xl) << 6;
            s_idx[base + 3] = (rh2 + xh) << 6;
        }
    }
    __syncthreads();

    const uint2* __restrict__ feat =
        (const uint2*)g_nhwc_h + (size_t)b * (HH * WW * (CCH / 4))
        + (c0 / 4) + cgrp;

    const unsigned long long pol = mk_evict_last_policy();

    // ---- Stage B: gather loop, 8 x 8B evict_last loads in flight/phase ----
    for (int bin = bslice; bin < NBINS; bin += 8) {
        float a0 = 0.f, a1 = 0.f, a2 = 0.f, a3 = 0.f;

#pragma unroll
        for (int sp = 0; sp < 2; ++sp) {
            const int base = (bin * 2 + sp) * 8;
            const int4   i01 = *(const int4*)&s_idx[base];
            const int4   i23 = *(const int4*)&s_idx[base + 4];
            const float4 w01 = *(const float4*)&s_w[base];
            const float4 w23 = *(const float4*)&s_w[base + 4];

            uint2 v[8];
            v[0] = ldg_el(feat + i01.x, pol);
            v[1] = ldg_el(feat + i01.y, pol);
            v[2] = ldg_el(feat + i01.z, pol);
            v[3] = ldg_el(feat + i01.w, pol);
            v[4] = ldg_el(feat + i23.x, pol);
            v[5] = ldg_el(feat + i23.y, pol);
            v[6] = ldg_el(feat + i23.z, pol);
            v[7] = ldg_el(feat + i23.w, pol);

            const float wf[8] = {w01.x, w01.y, w01.z, w01.w,
                                 w23.x, w23.y, w23.z, w23.w};
#pragma unroll
            for (int i = 0; i < 8; ++i) {
                const __half2* hp = (const __half2*)&v[i];
                float2 f0 = __half22float2(hp[0]);
                float2 f1 = __half22float2(hp[1]);
                a0 = fmaf(wf[i], f0.x, a0);
                a1 = fmaf(wf[i], f0.y, a1);
                a2 = fmaf(wf[i], f1.x, a2);
                a3 = fmaf(wf[i], f1.y, a3);
            }
        }

        // One conflict-free STS.128 per bin (lane stride 49 % 8 == 1).
        s_out4[cgrp * NBINS + bin] = make_float4(a0, a1, a2, a3);
    }

    __syncthreads();
    // Flush: conflict-free LDS.128 + 4 coalesced scalar streaming stores
    // (output written once, never re-read -> keep it out of L2).
    float* o = out + (size_t)roi * (CCH * NBINS) + (size_t)c0 * NBINS;
    for (int i = tid; i < (CBLK / 4) * NBINS; i += 256) {
        const int g   = i / NBINS;       // channel quad
        const int bb  = i - g * NBINS;   // bin
        const float4 v = s_out4[i];
        float* og = o + (4 * g) * NBINS + bb;
        __stcs(og + 0 * NBINS, v.x);
        __stcs(og + 1 * NBINS, v.y);
        __stcs(og + 2 * NBINS, v.z);
        __stcs(og + 3 * NBINS, v.w);
    }
}

extern "C" void kernel_launch(void* const* d_in, const int* in_sizes, int n_in,
                              void* d_out, int out_size)
{
    const float* feat = (const float*)d_in[0];
    const float* rois = (const float*)d_in[1];
    if (in_sizes[0] == NROIS * 6) {
        rois = (const float*)d_in[0];
        feat = (const float*)d_in[1];
    }
    float* out = (float*)d_out;

    dim3 tg((HH * WW) / 128, CCH / 32, N_IMG);
    nchw_to_nhwc_h_kernel<<<tg, 256>>>(feat);

    dim3 gg(NROIS, CCH / CBLK, 1);
    roialign_rot_kernel<<<gg, 256>>>(rois, out);
}

// round 14
// speedup vs baseline: 1.2209x; 1.0552x over previous
#include <cuda_runtime.h>
#include <cuda_fp16.h>
#include <math.h>

#define N_IMG 2
#define CCH   256
#define HH    256
#define WW    256
#define PHB   7
#define PWB   7
#define NBINS (PHB * PWB)
#define NPHASE (NBINS * 2)
#define NROIS 1024
#define SCALE 0.25f
#define CBLK  128                 // channels per gather block

// 64 MB static scratch: NHWC features in fp16 (L2-resident working set).
__device__ uint4 g_nhwc_h[(size_t)N_IMG * HH * WW * CCH / 8];

// ---------------------------------------------------------------------------
// Kernel 1: NCHW fp32 -> NHWC fp16 transpose. __ldcs input reads keep the
// streaming read from evicting the freshly written NHWC cache from L2.
// ---------------------------------------------------------------------------
__global__ void __launch_bounds__(256) nchw_to_nhwc_h_kernel(const float* __restrict__ in)
{
    __shared__ float4 tile[128 * 8];
    const int n   = blockIdx.z;
    const int hw0 = blockIdx.x * 128;
    const int c0  = blockIdx.y * 32;
    const int t   = threadIdx.x;

    const float* src = in + (size_t)n * CCH * HH * WW;
    __half*      dst = (__half*)g_nhwc_h + (size_t)n * HH * WW * CCH;

    const int hw4 = t & 31;
    const int c4w = t >> 5;

    float vv[4][4];
#pragma unroll
    for (int j = 0; j < 4; ++j) {
        float4 ld = __ldcs((const float4*)(src + (size_t)(c0 + c4w * 4 + j) * (HH * WW)
                                               + hw0 + hw4 * 4));
        vv[j][0] = ld.x; vv[j][1] = ld.y; vv[j][2] = ld.z; vv[j][3] = ld.w;
    }
#pragma unroll
    for (int r = 0; r < 4; ++r) {
        float4 o = make_float4(vv[0][r], vv[1][r], vv[2][r], vv[3][r]);
        const int hw = hw4 * 4 + r;
        tile[hw * 8 + (c4w ^ ((hw >> 2) & 7))] = o;
    }
    __syncthreads();

#pragma unroll
    for (int k = 0; k < 2; ++k) {
        const int idx = t + k * 256;       // 0..511
        const int cq  = idx & 3;           // 8-channel group
        const int hw  = idx >> 2;
        const int sw  = (hw >> 2) & 7;
        float4 f0 = tile[hw * 8 + ((2 * cq)     ^ sw)];
        float4 f1 = tile[hw * 8 + ((2 * cq + 1) ^ sw)];
        __half2 h[4];
        h[0] = __floats2half2_rn(f0.x, f0.y);
        h[1] = __floats2half2_rn(f0.z, f0.w);
        h[2] = __floats2half2_rn(f1.x, f1.y);
        h[3] = __floats2half2_rn(f1.z, f1.w);
        *(uint4*)(dst + (size_t)(hw0 + hw) * CCH + c0 + cq * 8) = *(uint4*)h;
    }
}

// ---------------------------------------------------------------------------
// Kernel 2: rotated RoIAlign gather on fp16 NHWC features. Block =
// (roi, channel-half): 128 channels, 256 threads = 32 uint2-groups x 8
// bin-slices. Stage A hoists per-(bin,phase) indices + fp16 weights.
// Stage B: per-phase 8-deep load batches; weighted sums computed with
// packed HFMA2 in chains of 4 corners, widened into fp32 accumulators
// (halves the arithmetic instruction stream vs scalar cvt+FFMA).
// Conflict-free STS.128 staging; coalesced streaming flush.
// ---------------------------------------------------------------------------
__global__ void __launch_bounds__(256, 5) roialign_rot_kernel(
    const float* __restrict__ rois, float* __restrict__ out)
{
    __shared__ float4  s_out4[(CBLK / 4) * NBINS];  // 25088 B
    __shared__ int     s_idx[NPHASE * 8];           // 3136 B
    __shared__ __half2 s_wh [NPHASE * 8];           // 1568 B

    const int roi    = blockIdx.x;
    const int c0     = blockIdx.y * CBLK;      // 0 or 128
    const int tid    = threadIdx.x;
    const int cgrp   = tid & 31;               // uint2 channel group (4 halves)
    const int bslice = tid >> 5;               // 0..7

    const float* r = rois + roi * 6;
    const int b = (int)r[0];

    // ---- Stage A: per-(bin,phase) precompute by 98 threads ----
    if (tid < NPHASE) {
        const int bin = tid >> 1;
        const int sp  = tid & 1;
        const int ph  = bin / PWB;
        const int pw  = bin - ph * PWB;

        const float cx = fmaf(r[1], SCALE, -0.5f);
        const float cy = fmaf(r[2], SCALE, -0.5f);
        const float rw = r[3] * SCALE;
        const float rh = r[4] * SCALE;
        float sn, cs;
        sincosf(r[5], &sn, &cs);

        const float bin_h = rh * (1.0f / PHB);
        const float bin_w = rw * (1.0f / PWB);
        const float yy = -0.5f * rh + ((float)ph + ((float)sp + 0.5f) * 0.5f) * bin_h;

#pragma unroll
        for (int ix = 0; ix < 2; ++ix) {
            const float xx = -0.5f * rw + ((float)pw + ((float)ix + 0.5f) * 0.5f) * bin_w;
            float y = yy * cs - xx * sn + cy;
            float x = yy * sn + xx * cs + cx;

            const bool valid = (y > -1.0f) & (y < (float)HH) &
                               (x > -1.0f) & (x < (float)WW);
            y = fmaxf(y, 0.0f);
            x = fmaxf(x, 0.0f);

            int yl = (int)y;
            int xl = (int)x;
            int yh, xh; float ly, lx;
            if (yl >= HH - 1) { yl = HH - 1; yh = HH - 1; ly = 0.f; }
            else              { yh = yl + 1; ly = y - (float)yl; }
            if (xl >= WW - 1) { xl = WW - 1; xh = WW - 1; lx = 0.f; }
            else              { xh = xl + 1; lx = x - (float)xl; }

            const float vsc = valid ? 0.25f : 0.0f;   // folds the /4 mean
            const float hy = 1.f - ly, hx = 1.f - lx;
            const int base = tid * 8 + ix * 4;
            s_wh[base + 0] = __float2half2_rn(hy * hx * vsc);
            s_wh[base + 1] = __float2half2_rn(hy * lx * vsc);
            s_wh[base + 2] = __float2half2_rn(ly * hx * vsc);
            s_wh[base + 3] = __float2half2_rn(ly * lx * vsc);

            const int rl = yl * WW, rh2 = yh * WW;
            s_idx[base + 0] = (rl  + xl) << 6;   // * (CCH/4) uint2 units
            s_idx[base + 1] = (rl  + xh) << 6;
            s_idx[base + 2] = (rh2 + xl) << 6;
            s_idx[base + 3] = (rh2 + xh) << 6;
        }
    }
    __syncthreads();

    const uint2* __restrict__ feat =
        (const uint2*)g_nhwc_h + (size_t)b * (HH * WW * (CCH / 4))
        + (c0 / 4) + cgrp;

    // ---- Stage B: 8-deep load batches; HFMA2 chains of 4, fp32 widen ----
    for (int bin = bslice; bin < NBINS; bin += 8) {
        float2 a01 = make_float2(0.f, 0.f);
        float2 a23 = make_float2(0.f, 0.f);

#pragma unroll
        for (int sp = 0; sp < 2; ++sp) {
            const int base = (bin * 2 + sp) * 8;
            const int4  i01 = *(const int4*)&s_idx[base];
            const int4  i23 = *(const int4*)&s_idx[base + 4];
            // 8 half2 weights = 32B = two uint4 LDS.
            uint4 wr0 = *(const uint4*)&s_wh[base];
            uint4 wr1 = *(const uint4*)&s_wh[base + 4];
            const __half2* w2a = (const __half2*)&wr0;
            const __half2* w2b = (const __half2*)&wr1;

            uint2 v[8];
            v[0] = __ldg(feat + i01.x);
            v[1] = __ldg(feat + i01.y);
            v[2] = __ldg(feat + i01.z);
            v[3] = __ldg(feat + i01.w);
            v[4] = __ldg(feat + i23.x);
            v[5] = __ldg(feat + i23.y);
            v[6] = __ldg(feat + i23.z);
            v[7] = __ldg(feat + i23.w);

            // Chain 0: corners 0..3 in fp16, widen once.
            __half2 cl = __float2half2_rn(0.f);
            __half2 ch = __float2half2_rn(0.f);
#pragma unroll
            for (int i = 0; i < 4; ++i) {
                const __half2* hp = (const __half2*)&v[i];
                cl = __hfma2(w2a[i], hp[0], cl);
                ch = __hfma2(w2a[i], hp[1], ch);
            }
            {
                float2 fl = __half22float2(cl);
                float2 fh = __half22float2(ch);
                a01.x += fl.x; a01.y += fl.y;
                a23.x += fh.x; a23.y += fh.y;
            }
            // Chain 1: corners 4..7 in fp16, widen once.
            cl = __float2half2_rn(0.f);
            ch = __float2half2_rn(0.f);
#pragma unroll
            for (int i = 0; i < 4; ++i) {
                const __half2* hp = (const __half2*)&v[4 + i];
                cl = __hfma2(w2b[i], hp[0], cl);
                ch = __hfma2(w2b[i], hp[1], ch);
            }
            {
                float2 fl = __half22float2(cl);
                float2 fh = __half22float2(ch);
                a01.x += fl.x; a01.y += fl.y;
                a23.x += fh.x; a23.y += fh.y;
            }
        }

        // One conflict-free STS.128 per bin (lane stride 49 % 8 == 1).
        s_out4[cgrp * NBINS + bin] = make_float4(a01.x, a01.y, a23.x, a23.y);
    }

    __syncthreads();
    // Flush: conflict-free LDS.128 + 4 coalesced scalar streaming stores
    // (output written once, never re-read -> keep it out of L2).
    float* o = out + (size_t)roi * (CCH * NBINS) + (size_t)c0 * NBINS;
    for (int i = tid; i < (CBLK / 4) * NBINS; i += 256) {
        const int g   = i / NBINS;       // channel quad
        const int bb  = i - g * NBINS;   // bin
        const float4 v = s_out4[i];
        float* og = o + (4 * g) * NBINS + bb;
        __stcs(og + 0 * NBINS, v.x);
        __stcs(og + 1 * NBINS, v.y);
        __stcs(og + 2 * NBINS, v.z);
        __stcs(og + 3 * NBINS, v.w);
    }
}

extern "C" void kernel_launch(void* const* d_in, const int* in_sizes, int n_in,
                              void* d_out, int out_size)
{
    const float* feat = (const float*)d_in[0];
    const float* rois = (const float*)d_in[1];
    if (in_sizes[0] == NROIS * 6) {
        rois = (const float*)d_in[0];
        feat = (const float*)d_in[1];
    }
    float* out = (float*)d_out;

    dim3 tg((HH * WW) / 128, CCH / 32, N_IMG);
    nchw_to_nhwc_h_kernel<<<tg, 256>>>(feat);

    dim3 gg(NROIS, CCH / CBLK, 1);
    roialign_rot_kernel<<<gg, 256>>>(rois, out);
}